// round 16
// baseline (speedup 1.0000x reference)
#include <cuda_runtime.h>
#include <cuda_fp16.h>
#include <cstdint>

#define B_  256
#define P_  196
#define E_  2048
#define A_  512
#define M_  (B_*P_)   // 50176 = 392*128
#define BK  32        // k-halfs per tile
#define KT  (E_/BK)   // 64 iterations

// ---------------- device scratch (no allocs allowed) ----------------
__device__ float g_dec_att[B_*A_];              // dec@W_dec + b_dec + b_enc
__device__ __align__(16) __half g_Wt[A_*E_];    // W_enc^T as fp16, [n][k]
__device__ float g_partial[M_*4];               // per-128-col score partials

// ---------------- helpers ----------------
__device__ __forceinline__ uint32_t smem_u32(const void* p) {
    uint32_t a;
    asm("{ .reg .u64 t; cvta.to.shared.u64 t, %1; cvt.u32.u64 %0, t; }"
        : "=r"(a) : "l"(p));
    return a;
}
__device__ __forceinline__ uint32_t pack_h2(float x, float y) {
    __half2 p = __floats2half2_rn(x, y);
    return *reinterpret_cast<uint32_t*>(&p);
}
#define CP_ASYNC16(dst_u32, src_ptr) \
    asm volatile("cp.async.cg.shared.global [%0], [%1], 16;" \
                 :: "r"(dst_u32), "l"(src_ptr) : "memory")
#define CP_COMMIT()  asm volatile("cp.async.commit_group;" ::: "memory")
#define CP_WAIT0()   asm volatile("cp.async.wait_group 0;" ::: "memory")

#define LDSM_X4(r0, r1, r2, r3, addr) \
    asm volatile("ldmatrix.sync.aligned.m8n8.x4.shared.b16 {%0,%1,%2,%3}, [%4];" \
                 : "=r"(r0), "=r"(r1), "=r"(r2), "=r"(r3) : "r"(addr))

#define MMA_F16(d, a0, a1, a2, a3, b0, b1) \
    asm volatile("mma.sync.aligned.m16n8k16.row.col.f32.f16.f16.f32 " \
                 "{%0,%1,%2,%3}, {%4,%5,%6,%7}, {%8,%9}, {%0,%1,%2,%3};" \
                 : "+f"((d)[0]), "+f"((d)[1]), "+f"((d)[2]), "+f"((d)[3]) \
                 : "r"(a0), "r"(a1), "r"(a2), "r"(a3), "r"(b0), "r"(b1))

// ---------------------------------------------------------------------------
// prep: blocks [0,256)   : transpose W_enc -> g_Wt, 64x64 tile per block
//                          (32 k-tiles x 8 n-tiles; 4 elems/thread, coalesced)
//       blocks [256,384) : dec_att, 2 batches/block, 1024 thr.
// ---------------------------------------------------------------------------
__global__ __launch_bounds__(1024)
void prep_kernel(const float* __restrict__ W_enc,
                 const float* __restrict__ dec_h,
                 const float* __restrict__ W_dec,
                 const float* __restrict__ b_dec,
                 const float* __restrict__ b_enc) {
    __shared__ float t[64][65];
    __shared__ float s_h[2][512];
    __shared__ float s_part[2][512];
    int bid = blockIdx.x;
    int tid = threadIdx.x;
    if (bid < 256) {
        // 32 k-tiles x 8 n-tiles of 64x64  (k tiles: bid&31, n tiles: bid>>5 in [0,8))
        int kt = (bid & 31) * 64, nt = (bid >> 5) * 64;
        {   // load: thread (ty=row 0..63, tx=float4 col 0..15)
            int tx = tid & 15, ty = tid >> 4;
            float4 v = *(const float4*)(W_enc + (size_t)(kt + ty) * A_ + nt + tx * 4);
            t[ty][tx * 4 + 0] = v.x;
            t[ty][tx * 4 + 1] = v.y;
            t[ty][tx * 4 + 2] = v.z;
            t[ty][tx * 4 + 3] = v.w;
        }
        __syncthreads();
        {   // store: thread (n=tid>>4, q=tid&15) writes 4 halfs along k
            int n = tid >> 4, q = tid & 15;
            uint2 h;
            h.x = pack_h2(t[4 * q + 0][n], t[4 * q + 1][n]);
            h.y = pack_h2(t[4 * q + 2][n], t[4 * q + 3][n]);
            *(uint2*)(g_Wt + (size_t)(nt + n) * E_ + kt + 4 * q) = h;
        }
    } else {
        int b0 = (bid - 256) * 2;           // 2 batches per block
        {
            int bb = tid >> 9, d = tid & 511;
            s_h[bb][d] = dec_h[(b0 + bb) * 512 + d];
        }
        __syncthreads();
        int a  = tid & 511;
        int dh = tid >> 9;                  // d-half 0/1
        float acc0 = 0.f, acc1 = 0.f;
        int d0 = dh * 256;
        const float* w = W_dec + (size_t)d0 * A_ + a;
#pragma unroll 4
        for (int i = 0; i < 256; i++) {
            float wv = w[(size_t)i * A_];
            acc0 = fmaf(s_h[0][d0 + i], wv, acc0);
            acc1 = fmaf(s_h[1][d0 + i], wv, acc1);
        }
        if (dh) { s_part[0][a] = acc0; s_part[1][a] = acc1; }
        __syncthreads();
        if (!dh) {
            float bias = b_dec[a] + b_enc[a];
            g_dec_att[(b0 + 0) * A_ + a] = acc0 + s_part[0][a] + bias;
            g_dec_att[(b0 + 1) * A_ + a] = acc1 + s_part[1][a] + bias;
        }
    }
}

// ---------------------------------------------------------------------------
// Fused scores GEMM, fp16 tensor path (exact R9 config: BK=32, 2-stage,
// 80 B pitch, 2 CTAs/SM).  Epilogue: relu(C+dec)·W_att -> g_partial.
// ---------------------------------------------------------------------------
#define PITCH   80                         // bytes per smem row (40 halfs)
#define TILE_SZ (128*PITCH)                // 10240 B per matrix tile
#define STAGE_B (2*TILE_SZ)                // 20480 B (A+B)
#define OFF_F32 (2*STAGE_B)                // 40960: float scratch region
#define SMEM_BYTES (OFF_F32 + 896*4)       // 44,544 B

__global__ __launch_bounds__(256, 2)
void scores_mma(const float* __restrict__ enc, const float* __restrict__ W_att) {
    extern __shared__ char sm[];
    const uint32_t sb = smem_u32(sm);

    const int tid  = threadIdx.x;
    const int lane = tid & 31, wid = tid >> 5;
    const int qr = lane >> 2, qc = lane & 3;
    const int wm = wid >> 2, wn = wid & 3;          // 2 x 4 warp grid
    const int nT = blockIdx.x, mT = blockIdx.y;
    const int mBase = mT * 128, nBase = nT * 128;
    const int b0 = mBase / P_;

    // A producer mapping: 4 passes, pass i: row = (tid>>3)+32i, 4 fp32 cols
    const int arow = tid >> 3, ac = tid & 7;

    float* s_dec  = (float*)(sm + OFF_F32);         // 256
    float* s_watt = s_dec + 256;                    // 128
    float* s_red  = s_watt + 128;                   // 512

    // ldmatrix thread-invariant byte offsets (within a tile)
    const uint32_t a_off = (uint32_t)((wm * 64 + (lane & 15)) * PITCH
                                      + (lane >> 4) * 16);
    const uint32_t b_off = (uint32_t)((wn * 32 + (lane & 7) + ((lane >> 4) << 3))
                                      * PITCH + ((lane >> 3) & 1) * 16);

    // ---------------- prologue: stage 0 ----------------
    {
#pragma unroll
        for (int i = 0; i < 4; i++) {
            int r = arow + 32 * i;
            float4 v = *(const float4*)(enc + (size_t)(mBase + r) * E_ + ac * 4);
            uint2 h = { pack_h2(v.x, v.y), pack_h2(v.z, v.w) };
            *(uint2*)(sm + r * PITCH + ac * 8) = h;
        }
        if (tid < 128) {
            const __half* bsrc = g_Wt + (size_t)(nBase + tid) * E_;
            uint32_t bdst = sb + TILE_SZ + (uint32_t)(tid * PITCH);
#pragma unroll
            for (int j = 0; j < 4; j++)
                CP_ASYNC16(bdst + j * 16, bsrc + j * 8);
        }
        CP_COMMIT();
    }
    // dec rows (2 batches) + W_att slice
    {
        int bb = b0 + (tid >> 7);
        if (bb >= B_) bb = B_ - 1;
        s_dec[tid] = g_dec_att[bb * A_ + nBase + (tid & 127)];
        if (tid < 128) s_watt[tid] = W_att[nBase + tid];
    }
    CP_WAIT0();
    __syncthreads();

    float acc[4][4][4];
#pragma unroll
    for (int mi = 0; mi < 4; mi++)
#pragma unroll
        for (int ni = 0; ni < 4; ni++)
#pragma unroll
            for (int j = 0; j < 4; j++) acc[mi][ni][j] = 0.f;

    // ---------------- main loop (64 iterations of BK=32) ----------------
    for (int kt = 0; kt < KT; kt++) {
        const uint32_t aBase = sb + (kt & 1) * STAGE_B;
        const uint32_t bBase = aBase + TILE_SZ;
        const int k0n = (kt + 1) * BK;
        const bool more = (kt < KT - 1);
        uint2 ah[4];

        if (more) {
            // A prefetch: LDG + immediate cvt to half (8 u32 staged)
#pragma unroll
            for (int i = 0; i < 4; i++) {
                float4 v = *(const float4*)(enc + (size_t)(mBase + arow + 32 * i) * E_
                                            + k0n + ac * 4);
                ah[i].x = pack_h2(v.x, v.y);
                ah[i].y = pack_h2(v.z, v.w);
            }
            if (tid < 128) {
                const __half* bsrc = g_Wt + (size_t)(nBase + tid) * E_ + k0n;
                uint32_t bdst = sb + ((kt & 1) ^ 1) * STAGE_B + TILE_SZ
                              + (uint32_t)(tid * PITCH);
#pragma unroll
                for (int j = 0; j < 4; j++)
                    CP_ASYNC16(bdst + j * 16, bsrc + j * 8);
            }
            CP_COMMIT();
        }

#pragma unroll
        for (int ks = 0; ks < 2; ks++) {
            uint32_t af[4][4], bf[2][4];
#pragma unroll
            for (int mi = 0; mi < 4; mi++)
                LDSM_X4(af[mi][0], af[mi][1], af[mi][2], af[mi][3],
                        aBase + a_off + (uint32_t)(mi * 16 * PITCH + ks * 32));
#pragma unroll
            for (int np = 0; np < 2; np++)
                LDSM_X4(bf[np][0], bf[np][1], bf[np][2], bf[np][3],
                        bBase + b_off + (uint32_t)(np * 16 * PITCH + ks * 32));
#pragma unroll
            for (int mi = 0; mi < 4; mi++)
#pragma unroll
                for (int ni = 0; ni < 4; ni++)
                    MMA_F16(acc[mi][ni],
                            af[mi][0], af[mi][1], af[mi][2], af[mi][3],
                            bf[ni >> 1][(ni & 1) * 2], bf[ni >> 1][(ni & 1) * 2 + 1]);
        }

        if (more) {
            char* An = sm + ((kt & 1) ^ 1) * STAGE_B;
#pragma unroll
            for (int i = 0; i < 4; i++)
                *(uint2*)(An + (arow + 32 * i) * PITCH + ac * 8) = ah[i];
            CP_WAIT0();
        }
        __syncthreads();
    }

    // ---------------- epilogue: relu(+dec)·W_att, per-row partials ----------------
#pragma unroll
    for (int mi = 0; mi < 4; mi++) {
#pragma unroll
        for (int half = 0; half < 2; half++) {
            int rl = wm * 64 + mi * 16 + qr + half * 8;
            int bloc = (mBase + rl) / P_ - b0;          // 0 or 1
            const float* drow = s_dec + bloc * 128;
            float s = 0.f;
#pragma unroll
            for (int ni = 0; ni < 4; ni++) {
#pragma unroll
                for (int j = 0; j < 2; j++) {
                    int c = wn * 32 + ni * 8 + qc * 2 + j;
                    float v = acc[mi][ni][half * 2 + j] + drow[c];
                    v = fmaxf(v, 0.f);
                    s = fmaf(v, s_watt[c], s);
                }
            }
            s += __shfl_xor_sync(0xffffffffu, s, 1);
            s += __shfl_xor_sync(0xffffffffu, s, 2);
            if (qc == 0) s_red[rl * 4 + wn] = s;
        }
    }
    __syncthreads();
    if (tid < 128) {
        const float* p = s_red + tid * 4;
        g_partial[(size_t)(mBase + tid) * 4 + nT] = p[0] + p[1] + p[2] + p[3];
    }
}

// ---------------------------------------------------------------------------
// context (softmax fused): per block (e-chunk, b) — recompute softmax from
// g_partial, then ctx = alpha @ enc with 4-deep load MLP.
// grid (4, 256) x 256 threads; two 98-long p-halves combined via smem.
// Block x==0 writes alpha.
// ---------------------------------------------------------------------------
__global__ __launch_bounds__(256)
void context_kernel(const float* __restrict__ enc,
                    float* __restrict__ ctx, float* __restrict__ alpha_out) {
    __shared__ float  s_a[P_];
    __shared__ float  s_red[256];
    __shared__ float4 s_part[128];
    int b = blockIdx.y;
    int tid = threadIdx.x;

    // ---- fused softmax over P=196 (b_att constant cancels) ----
    float sc = 0.f, v = -1e30f;
    if (tid < P_) {
        const float* p = &g_partial[(size_t)(b * P_ + tid) * 4];
        sc = p[0] + p[1] + p[2] + p[3];
        v  = sc;
    }
    s_red[tid] = v;
    __syncthreads();
    for (int o = 128; o > 0; o >>= 1) {
        if (tid < o) s_red[tid] = fmaxf(s_red[tid], s_red[tid + o]);
        __syncthreads();
    }
    float mx = s_red[0];
    __syncthreads();
    float e = (tid < P_) ? __expf(sc - mx) : 0.f;
    s_red[tid] = e;
    __syncthreads();
    for (int o = 128; o > 0; o >>= 1) {
        if (tid < o) s_red[tid] += s_red[tid + o];
        __syncthreads();
    }
    float inv = 1.f / s_red[0];
    if (tid < P_) {
        float a = e * inv;
        s_a[tid] = a;
        if (blockIdx.x == 0) alpha_out[b * P_ + tid] = a;
    }
    __syncthreads();

    // ---- weighted sum over fp32 enc (4 loads in flight) ----
    int e4 = blockIdx.x * 128 + (tid & 127);   // 0..511
    int ph = tid >> 7;                          // p-half 0 / 1
    const float4* base = (const float4*)(enc + (size_t)b * P_ * E_) + e4;
    float4 a0 = {0, 0, 0, 0}, a1 = {0, 0, 0, 0};
    float4 a2 = {0, 0, 0, 0}, a3 = {0, 0, 0, 0};
    int p0 = ph * 98;
    // 98 = 24*4 + 2
    for (int i = 0; i < 24; i++) {
        int p = p0 + i * 4;
        float4 v0 = base[(size_t)p * (E_ / 4)];
        float4 v1 = base[(size_t)(p + 1) * (E_ / 4)];
        float4 v2 = base[(size_t)(p + 2) * (E_ / 4)];
        float4 v3 = base[(size_t)(p + 3) * (E_ / 4)];
        float w0 = s_a[p], w1 = s_a[p + 1], w2 = s_a[p + 2], w3 = s_a[p + 3];
        a0.x = fmaf(w0, v0.x, a0.x); a0.y = fmaf(w0, v0.y, a0.y);
        a0.z = fmaf(w0, v0.z, a0.z); a0.w = fmaf(w0, v0.w, a0.w);
        a1.x = fmaf(w1, v1.x, a1.x); a1.y = fmaf(w1, v1.y, a1.y);
        a1.z = fmaf(w1, v1.z, a1.z); a1.w = fmaf(w1, v1.w, a1.w);
        a2.x = fmaf(w2, v2.x, a2.x); a2.y = fmaf(w2, v2.y, a2.y);
        a2.z = fmaf(w2, v2.z, a2.z); a2.w = fmaf(w2, v2.w, a2.w);
        a3.x = fmaf(w3, v3.x, a3.x); a3.y = fmaf(w3, v3.y, a3.y);
        a3.z = fmaf(w3, v3.z, a3.z); a3.w = fmaf(w3, v3.w, a3.w);
    }
    {   // tail pair (p0+96, p0+97)
        int p = p0 + 96;
        float4 v0 = base[(size_t)p * (E_ / 4)];
        float4 v1 = base[(size_t)(p + 1) * (E_ / 4)];
        float w0 = s_a[p], w1 = s_a[p + 1];
        a0.x = fmaf(w0, v0.x, a0.x); a0.y = fmaf(w0, v0.y, a0.y);
        a0.z = fmaf(w0, v0.z, a0.z); a0.w = fmaf(w0, v0.w, a0.w);
        a1.x = fmaf(w1, v1.x, a1.x); a1.y = fmaf(w1, v1.y, a1.y);
        a1.z = fmaf(w1, v1.z, a1.z); a1.w = fmaf(w1, v1.w, a1.w);
    }
    float4 r = { (a0.x + a1.x) + (a2.x + a3.x),
                 (a0.y + a1.y) + (a2.y + a3.y),
                 (a0.z + a1.z) + (a2.z + a3.z),
                 (a0.w + a1.w) + (a2.w + a3.w) };
    if (ph) s_part[tid & 127] = r;
    __syncthreads();
    if (!ph) {
        float4 o = s_part[tid];
        r.x += o.x; r.y += o.y; r.z += o.z; r.w += o.w;
        ((float4*)(ctx + (size_t)b * E_))[e4] = r;
    }
}

// ---------------------------------------------------------------------------
extern "C" void kernel_launch(void* const* d_in, const int* in_sizes, int n_in,
                              void* d_out, int out_size) {
    const float* enc   = (const float*)d_in[0];
    const float* dech  = (const float*)d_in[1];
    const float* W_enc = (const float*)d_in[2];
    const float* b_enc = (const float*)d_in[3];
    const float* W_dec = (const float*)d_in[4];
    const float* b_dec = (const float*)d_in[5];
    const float* W_att = (const float*)d_in[6];
    // d_in[7] = b_att: constant shift, cancels in softmax.

    float* ctx   = (float*)d_out;            // [256, 2048]
    float* alpha = (float*)d_out + B_ * E_;  // [256, 196]

    cudaFuncSetAttribute(scores_mma, cudaFuncAttributeMaxDynamicSharedMemorySize,
                         SMEM_BYTES);

    prep_kernel<<<384, 1024>>>(W_enc, dech, W_dec, b_dec, b_enc);
    scores_mma<<<dim3(4, 392), 256, SMEM_BYTES>>>(enc, W_att);
    context_kernel<<<dim3(4, B_), 256>>>(enc, ctx, alpha);
}

// round 17
// speedup vs baseline: 1.0474x; 1.0474x over previous
#include <cuda_runtime.h>
#include <cuda_fp16.h>
#include <cstdint>

#define B_  256
#define P_  196
#define E_  2048
#define A_  512
#define M_  (B_*P_)   // 50176 = 392*128
#define BK  32        // k-halfs per tile
#define KT  (E_/BK)   // 64 iterations

// ---------------- device scratch (no allocs allowed) ----------------
__device__ float g_dec_att[B_*A_];              // dec@W_dec + b_dec + b_enc
__device__ __align__(16) __half g_Wt[A_*E_];    // W_enc^T as fp16, [n][k]
__device__ float g_partial[M_*4];               // per-128-col score partials

// ---------------- helpers ----------------
__device__ __forceinline__ uint32_t smem_u32(const void* p) {
    uint32_t a;
    asm("{ .reg .u64 t; cvta.to.shared.u64 t, %1; cvt.u32.u64 %0, t; }"
        : "=r"(a) : "l"(p));
    return a;
}
__device__ __forceinline__ uint32_t pack_h2(float x, float y) {
    __half2 p = __floats2half2_rn(x, y);
    return *reinterpret_cast<uint32_t*>(&p);
}
#define CP_ASYNC16(dst_u32, src_ptr) \
    asm volatile("cp.async.cg.shared.global [%0], [%1], 16;" \
                 :: "r"(dst_u32), "l"(src_ptr) : "memory")
#define CP_COMMIT()  asm volatile("cp.async.commit_group;" ::: "memory")
#define CP_WAIT0()   asm volatile("cp.async.wait_group 0;" ::: "memory")

#define LDSM_X4(r0, r1, r2, r3, addr) \
    asm volatile("ldmatrix.sync.aligned.m8n8.x4.shared.b16 {%0,%1,%2,%3}, [%4];" \
                 : "=r"(r0), "=r"(r1), "=r"(r2), "=r"(r3) : "r"(addr))

#define MMA_F16(d, a0, a1, a2, a3, b0, b1) \
    asm volatile("mma.sync.aligned.m16n8k16.row.col.f32.f16.f16.f32 " \
                 "{%0,%1,%2,%3}, {%4,%5,%6,%7}, {%8,%9}, {%0,%1,%2,%3};" \
                 : "+f"((d)[0]), "+f"((d)[1]), "+f"((d)[2]), "+f"((d)[3]) \
                 : "r"(a0), "r"(a1), "r"(a2), "r"(a3), "r"(b0), "r"(b1))

// ---------------------------------------------------------------------------
// prep: blocks [0,256)   : transpose W_enc -> g_Wt, 64x64 tile per block
//       blocks [256,512) : dec_att, 1 batch/block, threads=(a:512, dh:2),
//                          two interleaved 128-deep chains, unroll 8.
// ---------------------------------------------------------------------------
__global__ __launch_bounds__(1024)
void prep_kernel(const float* __restrict__ W_enc,
                 const float* __restrict__ dec_h,
                 const float* __restrict__ W_dec,
                 const float* __restrict__ b_dec,
                 const float* __restrict__ b_enc) {
    __shared__ float t[64][65];
    __shared__ float s_h[512];
    __shared__ float s_part[512];
    int bid = blockIdx.x;
    int tid = threadIdx.x;
    if (bid < 256) {
        // 32 k-tiles x 8 n-tiles of 64x64
        int kt = (bid & 31) * 64, nt = (bid >> 5) * 64;
        {   // load: thread (ty=row 0..63, tx=float4 col 0..15)
            int tx = tid & 15, ty = tid >> 4;
            float4 v = *(const float4*)(W_enc + (size_t)(kt + ty) * A_ + nt + tx * 4);
            t[ty][tx * 4 + 0] = v.x;
            t[ty][tx * 4 + 1] = v.y;
            t[ty][tx * 4 + 2] = v.z;
            t[ty][tx * 4 + 3] = v.w;
        }
        __syncthreads();
        {   // store: thread (n=tid>>4, q=tid&15) writes 4 halfs along k
            int n = tid >> 4, q = tid & 15;
            uint2 h;
            h.x = pack_h2(t[4 * q + 0][n], t[4 * q + 1][n]);
            h.y = pack_h2(t[4 * q + 2][n], t[4 * q + 3][n]);
            *(uint2*)(g_Wt + (size_t)(nt + n) * E_ + kt + 4 * q) = h;
        }
    } else {
        int b = bid - 256;                   // 1 batch per block
        if (tid < 512) s_h[tid] = dec_h[b * 512 + tid];
        __syncthreads();
        int a  = tid & 511;
        int dh = tid >> 9;                   // d-half 0/1
        int d0 = dh * 256;
        float acc0 = 0.f, acc1 = 0.f;
        const float* w = W_dec + (size_t)d0 * A_ + a;
#pragma unroll 8
        for (int i = 0; i < 256; i += 2) {
            acc0 = fmaf(s_h[d0 + i],     w[(size_t)i * A_],       acc0);
            acc1 = fmaf(s_h[d0 + i + 1], w[(size_t)(i + 1) * A_], acc1);
        }
        if (dh) s_part[a] = acc0 + acc1;
        __syncthreads();
        if (!dh) {
            float bias = b_dec[a] + b_enc[a];
            g_dec_att[b * A_ + a] = (acc0 + acc1) + s_part[a] + bias;
        }
    }
}

// ---------------------------------------------------------------------------
// Fused scores GEMM, fp16 tensor path (exact R9 config: BK=32, 2-stage,
// 80 B pitch, 2 CTAs/SM).  Epilogue: relu(C+dec)·W_att -> g_partial.
// ---------------------------------------------------------------------------
#define PITCH   80                         // bytes per smem row (40 halfs)
#define TILE_SZ (128*PITCH)                // 10240 B per matrix tile
#define STAGE_B (2*TILE_SZ)                // 20480 B (A+B)
#define OFF_F32 (2*STAGE_B)                // 40960: float scratch region
#define SMEM_BYTES (OFF_F32 + 896*4)       // 44,544 B

__global__ __launch_bounds__(256, 2)
void scores_mma(const float* __restrict__ enc, const float* __restrict__ W_att) {
    extern __shared__ char sm[];
    const uint32_t sb = smem_u32(sm);

    const int tid  = threadIdx.x;
    const int lane = tid & 31, wid = tid >> 5;
    const int qr = lane >> 2, qc = lane & 3;
    const int wm = wid >> 2, wn = wid & 3;          // 2 x 4 warp grid
    const int nT = blockIdx.x, mT = blockIdx.y;
    const int mBase = mT * 128, nBase = nT * 128;
    const int b0 = mBase / P_;

    // A producer mapping: 4 passes, pass i: row = (tid>>3)+32i, 4 fp32 cols
    const int arow = tid >> 3, ac = tid & 7;

    float* s_dec  = (float*)(sm + OFF_F32);         // 256
    float* s_watt = s_dec + 256;                    // 128
    float* s_red  = s_watt + 128;                   // 512

    // ldmatrix thread-invariant byte offsets (within a tile)
    const uint32_t a_off = (uint32_t)((wm * 64 + (lane & 15)) * PITCH
                                      + (lane >> 4) * 16);
    const uint32_t b_off = (uint32_t)((wn * 32 + (lane & 7) + ((lane >> 4) << 3))
                                      * PITCH + ((lane >> 3) & 1) * 16);

    // ---------------- prologue: stage 0 ----------------
    {
#pragma unroll
        for (int i = 0; i < 4; i++) {
            int r = arow + 32 * i;
            float4 v = *(const float4*)(enc + (size_t)(mBase + r) * E_ + ac * 4);
            uint2 h = { pack_h2(v.x, v.y), pack_h2(v.z, v.w) };
            *(uint2*)(sm + r * PITCH + ac * 8) = h;
        }
        if (tid < 128) {
            const __half* bsrc = g_Wt + (size_t)(nBase + tid) * E_;
            uint32_t bdst = sb + TILE_SZ + (uint32_t)(tid * PITCH);
#pragma unroll
            for (int j = 0; j < 4; j++)
                CP_ASYNC16(bdst + j * 16, bsrc + j * 8);
        }
        CP_COMMIT();
    }
    // dec rows (2 batches) + W_att slice
    {
        int bb = b0 + (tid >> 7);
        if (bb >= B_) bb = B_ - 1;
        s_dec[tid] = g_dec_att[bb * A_ + nBase + (tid & 127)];
        if (tid < 128) s_watt[tid] = W_att[nBase + tid];
    }
    CP_WAIT0();
    __syncthreads();

    float acc[4][4][4];
#pragma unroll
    for (int mi = 0; mi < 4; mi++)
#pragma unroll
        for (int ni = 0; ni < 4; ni++)
#pragma unroll
            for (int j = 0; j < 4; j++) acc[mi][ni][j] = 0.f;

    // ---------------- main loop (64 iterations of BK=32) ----------------
    for (int kt = 0; kt < KT; kt++) {
        const uint32_t aBase = sb + (kt & 1) * STAGE_B;
        const uint32_t bBase = aBase + TILE_SZ;
        const int k0n = (kt + 1) * BK;
        const bool more = (kt < KT - 1);
        uint2 ah[4];

        if (more) {
            // A prefetch: LDG + immediate cvt to half (8 u32 staged)
#pragma unroll
            for (int i = 0; i < 4; i++) {
                float4 v = *(const float4*)(enc + (size_t)(mBase + arow + 32 * i) * E_
                                            + k0n + ac * 4);
                ah[i].x = pack_h2(v.x, v.y);
                ah[i].y = pack_h2(v.z, v.w);
            }
            if (tid < 128) {
                const __half* bsrc = g_Wt + (size_t)(nBase + tid) * E_ + k0n;
                uint32_t bdst = sb + ((kt & 1) ^ 1) * STAGE_B + TILE_SZ
                              + (uint32_t)(tid * PITCH);
#pragma unroll
                for (int j = 0; j < 4; j++)
                    CP_ASYNC16(bdst + j * 16, bsrc + j * 8);
            }
            CP_COMMIT();
        }

#pragma unroll
        for (int ks = 0; ks < 2; ks++) {
            uint32_t af[4][4], bf[2][4];
#pragma unroll
            for (int mi = 0; mi < 4; mi++)
                LDSM_X4(af[mi][0], af[mi][1], af[mi][2], af[mi][3],
                        aBase + a_off + (uint32_t)(mi * 16 * PITCH + ks * 32));
#pragma unroll
            for (int np = 0; np < 2; np++)
                LDSM_X4(bf[np][0], bf[np][1], bf[np][2], bf[np][3],
                        bBase + b_off + (uint32_t)(np * 16 * PITCH + ks * 32));
#pragma unroll
            for (int mi = 0; mi < 4; mi++)
#pragma unroll
                for (int ni = 0; ni < 4; ni++)
                    MMA_F16(acc[mi][ni],
                            af[mi][0], af[mi][1], af[mi][2], af[mi][3],
                            bf[ni >> 1][(ni & 1) * 2], bf[ni >> 1][(ni & 1) * 2 + 1]);
        }

        if (more) {
            char* An = sm + ((kt & 1) ^ 1) * STAGE_B;
#pragma unroll
            for (int i = 0; i < 4; i++)
                *(uint2*)(An + (arow + 32 * i) * PITCH + ac * 8) = ah[i];
            CP_WAIT0();
        }
        __syncthreads();
    }

    // ---------------- epilogue: relu(+dec)·W_att, per-row partials ----------------
#pragma unroll
    for (int mi = 0; mi < 4; mi++) {
#pragma unroll
        for (int half = 0; half < 2; half++) {
            int rl = wm * 64 + mi * 16 + qr + half * 8;
            int bloc = (mBase + rl) / P_ - b0;          // 0 or 1
            const float* drow = s_dec + bloc * 128;
            float s = 0.f;
#pragma unroll
            for (int ni = 0; ni < 4; ni++) {
#pragma unroll
                for (int j = 0; j < 2; j++) {
                    int c = wn * 32 + ni * 8 + qc * 2 + j;
                    float v = acc[mi][ni][half * 2 + j] + drow[c];
                    v = fmaxf(v, 0.f);
                    s = fmaf(v, s_watt[c], s);
                }
            }
            s += __shfl_xor_sync(0xffffffffu, s, 1);
            s += __shfl_xor_sync(0xffffffffu, s, 2);
            if (qc == 0) s_red[rl * 4 + wn] = s;
        }
    }
    __syncthreads();
    if (tid < 128) {
        const float* p = s_red + tid * 4;
        g_partial[(size_t)(mBase + tid) * 4 + nT] = p[0] + p[1] + p[2] + p[3];
    }
}

// ---------------------------------------------------------------------------
// context (softmax fused): per block (e-chunk, b) — recompute softmax from
// g_partial, then ctx = alpha @ enc (MLP-2, the measured-best form).
// grid (4, 256) x 256 threads; two 98-long p-halves combined via smem.
// Block x==0 writes alpha.
// ---------------------------------------------------------------------------
__global__ __launch_bounds__(256)
void context_kernel(const float* __restrict__ enc,
                    float* __restrict__ ctx, float* __restrict__ alpha_out) {
    __shared__ float  s_a[P_];
    __shared__ float  s_red[256];
    __shared__ float4 s_part[128];
    int b = blockIdx.y;
    int tid = threadIdx.x;

    // ---- fused softmax over P=196 (b_att constant cancels) ----
    float sc = 0.f, v = -1e30f;
    if (tid < P_) {
        const float* p = &g_partial[(size_t)(b * P_ + tid) * 4];
        sc = p[0] + p[1] + p[2] + p[3];
        v  = sc;
    }
    s_red[tid] = v;
    __syncthreads();
    for (int o = 128; o > 0; o >>= 1) {
        if (tid < o) s_red[tid] = fmaxf(s_red[tid], s_red[tid + o]);
        __syncthreads();
    }
    float mx = s_red[0];
    __syncthreads();
    float e = (tid < P_) ? __expf(sc - mx) : 0.f;
    s_red[tid] = e;
    __syncthreads();
    for (int o = 128; o > 0; o >>= 1) {
        if (tid < o) s_red[tid] += s_red[tid + o];
        __syncthreads();
    }
    float inv = 1.f / s_red[0];
    if (tid < P_) {
        float a = e * inv;
        s_a[tid] = a;
        if (blockIdx.x == 0) alpha_out[b * P_ + tid] = a;
    }
    __syncthreads();

    // ---- weighted sum over fp32 enc (MLP-2) ----
    int e4 = blockIdx.x * 128 + (tid & 127);   // 0..511
    int ph = tid >> 7;                          // p-half 0 / 1
    const float4* base = (const float4*)(enc + (size_t)b * P_ * E_) + e4;
    float4 a0 = {0, 0, 0, 0}, a1 = {0, 0, 0, 0};
    int p0 = ph * 98;
    for (int i = 0; i < 49; i++) {
        int p = p0 + i * 2;
        float4 v0 = base[(size_t)p * (E_ / 4)];
        float4 v1 = base[(size_t)(p + 1) * (E_ / 4)];
        float w0 = s_a[p], w1 = s_a[p + 1];
        a0.x = fmaf(w0, v0.x, a0.x); a0.y = fmaf(w0, v0.y, a0.y);
        a0.z = fmaf(w0, v0.z, a0.z); a0.w = fmaf(w0, v0.w, a0.w);
        a1.x = fmaf(w1, v1.x, a1.x); a1.y = fmaf(w1, v1.y, a1.y);
        a1.z = fmaf(w1, v1.z, a1.z); a1.w = fmaf(w1, v1.w, a1.w);
    }
    float4 r = { a0.x + a1.x, a0.y + a1.y, a0.z + a1.z, a0.w + a1.w };
    if (ph) s_part[tid & 127] = r;
    __syncthreads();
    if (!ph) {
        float4 o = s_part[tid];
        r.x += o.x; r.y += o.y; r.z += o.z; r.w += o.w;
        ((float4*)(ctx + (size_t)b * E_))[e4] = r;
    }
}

// ---------------------------------------------------------------------------
extern "C" void kernel_launch(void* const* d_in, const int* in_sizes, int n_in,
                              void* d_out, int out_size) {
    const float* enc   = (const float*)d_in[0];
    const float* dech  = (const float*)d_in[1];
    const float* W_enc = (const float*)d_in[2];
    const float* b_enc = (const float*)d_in[3];
    const float* W_dec = (const float*)d_in[4];
    const float* b_dec = (const float*)d_in[5];
    const float* W_att = (const float*)d_in[6];
    // d_in[7] = b_att: constant shift, cancels in softmax.

    float* ctx   = (float*)d_out;            // [256, 2048]
    float* alpha = (float*)d_out + B_ * E_;  // [256, 196]

    cudaFuncSetAttribute(scores_mma, cudaFuncAttributeMaxDynamicSharedMemorySize,
                         SMEM_BYTES);

    prep_kernel<<<512, 1024>>>(W_enc, dech, W_dec, b_dec, b_enc);
    scores_mma<<<dim3(4, 392), 256, SMEM_BYTES>>>(enc, W_att);
    context_kernel<<<dim3(4, B_), 256>>>(enc, ctx, alpha);
}